// round 16
// baseline (speedup 1.0000x reference)
#include <cuda_runtime.h>
#include <cuda_fp16.h>
#include <cstdint>

// ---------------------------------------------------------------------------
// Problem constants
// ---------------------------------------------------------------------------
#define OUT_F 4096
#define IN_F  4096
#define MDIM  (8 * 2048)   // B*S = 16384

// 160MB module-static scratch (fp16 operands)
__device__ __half g_Wh[(size_t)OUT_F * IN_F];    // dequantized W [OUT_F][IN_F], fp16
__device__ __half g_Ah[(size_t)MDIM * IN_F];     // x [MDIM][IN_F], fp16

// ---------------------------------------------------------------------------
// Prepass 1: dequantize W_q -> g_Wh (fp16 RN).
// W_q flat IS [OUT_F][IN_F] row-major (flat = o*4096 + i). Param p = (o&63)*4096 + i.
// ---------------------------------------------------------------------------
__global__ void dequant_kernel(const int* __restrict__ Wq,
                               const float* __restrict__ scale,
                               const float* __restrict__ zero) {
    int f = (blockIdx.x * blockDim.x + threadIdx.x) * 4;
    int o = f >> 12;
    int i = f & 4095;
    int p = ((o & 63) << 12) | i;

    int4   q = *reinterpret_cast<const int4*>(Wq + f);
    float4 z = *reinterpret_cast<const float4*>(zero + p);
    float4 s = *reinterpret_cast<const float4*>(scale + p);

    __half2 lo = __floats2half2_rn(((float)q.x - z.x) * s.x, ((float)q.y - z.y) * s.y);
    __half2 hi = __floats2half2_rn(((float)q.z - z.z) * s.z, ((float)q.w - z.w) * s.w);
    *reinterpret_cast<uint2*>(g_Wh + f) =
        make_uint2(*reinterpret_cast<uint32_t*>(&lo), *reinterpret_cast<uint32_t*>(&hi));
}

// Prepass 2: x -> g_Ah (fp16 RN)
__global__ void round_a_kernel(const float* __restrict__ x) {
    size_t f = (size_t)(blockIdx.x * blockDim.x + threadIdx.x) * 4;
    float4 v = *reinterpret_cast<const float4*>(x + f);
    __half2 lo = __floats2half2_rn(v.x, v.y);
    __half2 hi = __floats2half2_rn(v.z, v.w);
    *reinterpret_cast<uint2*>(g_Ah + f) =
        make_uint2(*reinterpret_cast<uint32_t*>(&lo), *reinterpret_cast<uint32_t*>(&hi));
}

// ---------------------------------------------------------------------------
// GEMM  C[m][n] = sum_k A[m][k] * W[n][k] + bias[n]
// fp16, block tile 256x128, BK=32, 512 threads = 16 warps in 4(m) x 4(n),
// warp tile 64x32, mma.m16n8k16.f16, 3-stage cp.async (wait_group 1).
// Single change vs R14: 16 warps (4/SMSP) instead of 8 (2/SMSP).
// ---------------------------------------------------------------------------
#define BM 256
#define BN 128
#define BK 32
#define STAGES 3
#define HSTRIDE 40                      // halfs/row (32 data + 8 pad) — conflict-free
#define A_STAGE (BM * HSTRIDE)          // 10240 halfs
#define B_STAGE (BN * HSTRIDE)          // 5120 halfs

__global__ void __launch_bounds__(512, 1)
gemm_f16_kernel(const float* __restrict__ bias, float* __restrict__ C) {
    extern __shared__ __align__(16) __half sh[];
    __half* Asm = sh;                        // [STAGES][BM][HSTRIDE]
    __half* Bsm = sh + STAGES * A_STAGE;     // [STAGES][BN][HSTRIDE]

    const __half* A  = g_Ah;
    const __half* Bw = g_Wh;

    const int tid  = threadIdx.x;
    const int bm   = blockIdx.y * BM;
    const int bn   = blockIdx.x * BN;
    const int warp = tid >> 5;          // 0..15
    const int lane = tid & 31;
    const int wm   = (warp & 3) * 64;   // warp m-offset (4 warps in m)
    const int wn   = (warp >> 2) * 32;  // warp n-offset (4 warps in n)
    const int grp  = lane >> 2;         // 0..7
    const int tig  = lane & 3;          // 0..3

    float c[4][4][4];
#pragma unroll
    for (int mt = 0; mt < 4; mt++)
#pragma unroll
        for (int nt = 0; nt < 4; nt++)
#pragma unroll
            for (int r = 0; r < 4; r++) c[mt][nt][r] = 0.0f;

    // global->shared: 64B rows, 4 threads/row (512 threads):
    // A: rows ldrow, ldrow+128 (2 per thread); B: row ldrow (1 per thread)
    const int ldrow = tid >> 2;        // 0..127
    const int ldc   = (tid & 3) * 8;   // half-col offset {0,8,16,24}

    const int NT = IN_F / BK;          // 128 k-tiles

#define LOAD_TILE(st, kt)                                                      \
    do {                                                                       \
        int gk = (kt) * BK + ldc;                                              \
        _Pragma("unroll")                                                      \
        for (int r = 0; r < 2; r++) {                                          \
            int row = ldrow + r * 128;                                         \
            uint32_t sa = (uint32_t)__cvta_generic_to_shared(                  \
                &Asm[(st) * A_STAGE + row * HSTRIDE + ldc]);                   \
            const __half* ga = A + (size_t)(bm + row) * IN_F + gk;             \
            asm volatile("cp.async.cg.shared.global [%0], [%1], 16;\n"         \
                         :: "r"(sa), "l"(ga));                                 \
        }                                                                      \
        {                                                                      \
            uint32_t sb = (uint32_t)__cvta_generic_to_shared(                  \
                &Bsm[(st) * B_STAGE + ldrow * HSTRIDE + ldc]);                 \
            const __half* gb = Bw + (size_t)(bn + ldrow) * IN_F + gk;          \
            asm volatile("cp.async.cg.shared.global [%0], [%1], 16;\n"         \
                         :: "r"(sb), "l"(gb));                                 \
        }                                                                      \
    } while (0)

    // prefetch 2 stages
    LOAD_TILE(0, 0);
    asm volatile("cp.async.commit_group;\n");
    LOAD_TILE(1, 1);
    asm volatile("cp.async.commit_group;\n");

    int st = 0;        // stage holding tile kt
    int ld = 2;        // stage to load tile kt+2 into

#pragma unroll 1
    for (int kt = 0; kt < NT; kt++) {
        asm volatile("cp.async.wait_group 1;\n");   // tile kt complete
        __syncthreads();   // all warps done with stage 'ld'

        if (kt + 2 < NT) LOAD_TILE(ld, kt + 2);
        asm volatile("cp.async.commit_group;\n");   // always commit: exact group count

        const __half* as = &Asm[st * A_STAGE];
        const __half* bs = &Bsm[st * B_STAGE];

#pragma unroll
        for (int kk = 0; kk < BK; kk += 16) {
            uint32_t af[4][4], bf[4][2];
#pragma unroll
            for (int mt = 0; mt < 4; mt++) {
                int row = wm + mt * 16 + grp;
                af[mt][0] = *reinterpret_cast<const uint32_t*>(&as[row * HSTRIDE + kk + 2 * tig]);
                af[mt][1] = *reinterpret_cast<const uint32_t*>(&as[(row + 8) * HSTRIDE + kk + 2 * tig]);
                af[mt][2] = *reinterpret_cast<const uint32_t*>(&as[row * HSTRIDE + kk + 2 * tig + 8]);
                af[mt][3] = *reinterpret_cast<const uint32_t*>(&as[(row + 8) * HSTRIDE + kk + 2 * tig + 8]);
            }
#pragma unroll
            for (int nt = 0; nt < 4; nt++) {
                int col = wn + nt * 8 + grp;
                bf[nt][0] = *reinterpret_cast<const uint32_t*>(&bs[col * HSTRIDE + kk + 2 * tig]);
                bf[nt][1] = *reinterpret_cast<const uint32_t*>(&bs[col * HSTRIDE + kk + 2 * tig + 8]);
            }
#pragma unroll
            for (int mt = 0; mt < 4; mt++)
#pragma unroll
                for (int nt = 0; nt < 4; nt++) {
                    asm volatile(
                        "mma.sync.aligned.m16n8k16.row.col.f32.f16.f16.f32 "
                        "{%0,%1,%2,%3}, {%4,%5,%6,%7}, {%8,%9}, {%0,%1,%2,%3};\n"
                        : "+f"(c[mt][nt][0]), "+f"(c[mt][nt][1]),
                          "+f"(c[mt][nt][2]), "+f"(c[mt][nt][3])
                        : "r"(af[mt][0]), "r"(af[mt][1]),
                          "r"(af[mt][2]), "r"(af[mt][3]),
                          "r"(bf[nt][0]), "r"(bf[nt][1]));
                }
        }

        // rotate stages (mod 3)
        st = (st == STAGES - 1) ? 0 : st + 1;
        ld = (ld == STAGES - 1) ? 0 : ld + 1;
    }

    // Epilogue: add bias, float2 stores (cols 2*tig, 2*tig+1 contiguous)
#pragma unroll
    for (int nt = 0; nt < 4; nt++) {
        int col = bn + wn + nt * 8 + tig * 2;
        float b0 = __ldg(bias + col);
        float b1 = __ldg(bias + col + 1);
#pragma unroll
        for (int mt = 0; mt < 4; mt++) {
            int row0 = bm + wm + mt * 16 + grp;
            float2 v0 = make_float2(c[mt][nt][0] + b0, c[mt][nt][1] + b1);
            float2 v1 = make_float2(c[mt][nt][2] + b0, c[mt][nt][3] + b1);
            *reinterpret_cast<float2*>(C + (size_t)row0 * OUT_F + col) = v0;
            *reinterpret_cast<float2*>(C + (size_t)(row0 + 8) * OUT_F + col) = v1;
        }
    }
}

// ---------------------------------------------------------------------------
// Launch
// ---------------------------------------------------------------------------
extern "C" void kernel_launch(void* const* d_in, const int* in_sizes, int n_in,
                              void* d_out, int out_size) {
    const float* x     = (const float*)d_in[0];  // [16384, 4096] fp32
    const int*   Wq    = (const int*)d_in[1];    // [64, 262144] int32 (u8 values)
    const float* scale = (const float*)d_in[2];  // [1, 262144]
    const float* zero  = (const float*)d_in[3];  // [1, 262144]
    const float* bias  = (const float*)d_in[4];  // [4096]
    float*       out   = (float*)d_out;          // [16384, 4096] fp32

    round_a_kernel<<<(int)((size_t)MDIM * IN_F / 4 / 256), 256>>>(x);
    dequant_kernel<<<(OUT_F * IN_F) / 4 / 256, 256>>>(Wq, scale, zero);

    const int smem_bytes = STAGES * (A_STAGE + B_STAGE) * (int)sizeof(__half);  // 92160
    cudaFuncSetAttribute(gemm_f16_kernel,
                         cudaFuncAttributeMaxDynamicSharedMemorySize, smem_bytes);

    dim3 grid(OUT_F / BN, MDIM / BM);   // (32, 64)
    gemm_f16_kernel<<<grid, 512, smem_bytes>>>(bias, out);
}

// round 17
// speedup vs baseline: 1.2190x; 1.2190x over previous
#include <cuda_runtime.h>
#include <cuda_fp16.h>
#include <cstdint>

// ---------------------------------------------------------------------------
// Problem constants
// ---------------------------------------------------------------------------
#define OUT_F 4096
#define IN_F  4096
#define MDIM  (8 * 2048)   // B*S = 16384

// 160MB module-static scratch (fp16 operands)
__device__ __half g_Wh[(size_t)OUT_F * IN_F];    // dequantized W [OUT_F][IN_F], fp16
__device__ __half g_Ah[(size_t)MDIM * IN_F];     // x [MDIM][IN_F], fp16

// ---------------------------------------------------------------------------
// Prepass 1: dequantize W_q -> g_Wh (fp16 RN), 8 elems/thread.
// W_q flat IS [OUT_F][IN_F] row-major (flat = o*4096 + i). Param p = (o&63)*4096 + i.
// ---------------------------------------------------------------------------
__global__ void dequant_kernel(const int* __restrict__ Wq,
                               const float* __restrict__ scale,
                               const float* __restrict__ zero) {
    int f = (blockIdx.x * blockDim.x + threadIdx.x) * 8;
    int o = f >> 12;
    int i = f & 4095;
    int p = ((o & 63) << 12) | i;

    int4   q0 = *reinterpret_cast<const int4*>(Wq + f);
    int4   q1 = *reinterpret_cast<const int4*>(Wq + f + 4);
    float4 z0 = *reinterpret_cast<const float4*>(zero + p);
    float4 z1 = *reinterpret_cast<const float4*>(zero + p + 4);
    float4 s0 = *reinterpret_cast<const float4*>(scale + p);
    float4 s1 = *reinterpret_cast<const float4*>(scale + p + 4);

    __half2 h0 = __floats2half2_rn(((float)q0.x - z0.x) * s0.x, ((float)q0.y - z0.y) * s0.y);
    __half2 h1 = __floats2half2_rn(((float)q0.z - z0.z) * s0.z, ((float)q0.w - z0.w) * s0.w);
    __half2 h2 = __floats2half2_rn(((float)q1.x - z1.x) * s1.x, ((float)q1.y - z1.y) * s1.y);
    __half2 h3 = __floats2half2_rn(((float)q1.z - z1.z) * s1.z, ((float)q1.w - z1.w) * s1.w);
    uint4 w;
    w.x = *reinterpret_cast<uint32_t*>(&h0);
    w.y = *reinterpret_cast<uint32_t*>(&h1);
    w.z = *reinterpret_cast<uint32_t*>(&h2);
    w.w = *reinterpret_cast<uint32_t*>(&h3);
    *reinterpret_cast<uint4*>(g_Wh + f) = w;
}

// Prepass 2: x -> g_Ah (fp16 RN)
__global__ void round_a_kernel(const float* __restrict__ x) {
    size_t f = (size_t)(blockIdx.x * blockDim.x + threadIdx.x) * 4;
    float4 v = *reinterpret_cast<const float4*>(x + f);
    __half2 lo = __floats2half2_rn(v.x, v.y);
    __half2 hi = __floats2half2_rn(v.z, v.w);
    *reinterpret_cast<uint2*>(g_Ah + f) =
        make_uint2(*reinterpret_cast<uint32_t*>(&lo), *reinterpret_cast<uint32_t*>(&hi));
}

// ---------------------------------------------------------------------------
// GEMM  C[m][n] = sum_k A[m][k] * W[n][k] + bias[n]
// fp16, block tile 256x128, BK=64 (this round's GEMM change), 8 warps (4m x 2n),
// warp tile 64x64, mma.m16n8k16.f16, 3-stage cp.async (wait_group 1).
// ---------------------------------------------------------------------------
#define BM 256
#define BN 128
#define BK 64
#define STAGES 3
#define HSTRIDE 72                      // halfs/row (64 data + 8 pad) — conflict-free
#define A_STAGE (BM * HSTRIDE)          // 18432 halfs
#define B_STAGE (BN * HSTRIDE)          // 9216 halfs

__global__ void __launch_bounds__(256, 1)
gemm_f16_kernel(const float* __restrict__ bias, float* __restrict__ C) {
    extern __shared__ __align__(16) __half sh[];
    __half* Asm = sh;                        // [STAGES][BM][HSTRIDE]
    __half* Bsm = sh + STAGES * A_STAGE;     // [STAGES][BN][HSTRIDE]

    const __half* A  = g_Ah;
    const __half* Bw = g_Wh;

    const int tid  = threadIdx.x;
    const int bm   = blockIdx.y * BM;
    const int bn   = blockIdx.x * BN;
    const int warp = tid >> 5;
    const int lane = tid & 31;
    const int wm   = (warp & 3) * 64;   // warp m-offset (4 warps in m)
    const int wn   = (warp >> 2) * 64;  // warp n-offset (2 warps in n)
    const int grp  = lane >> 2;         // 0..7
    const int tig  = lane & 3;          // 0..3

    float c[4][8][4];
#pragma unroll
    for (int mt = 0; mt < 4; mt++)
#pragma unroll
        for (int nt = 0; nt < 8; nt++)
#pragma unroll
            for (int r = 0; r < 4; r++) c[mt][nt][r] = 0.0f;

    // global->shared: 128B rows, 8 threads/row; A 8 rows/thread, B 4 rows/thread
    const int ldrow = tid >> 3;        // 0..31
    const int ldc   = (tid & 7) * 8;   // half-col offset {0,8,...,56}

    const int NT = IN_F / BK;          // 64 k-tiles

#define LOAD_TILE(st, kt)                                                      \
    do {                                                                       \
        int gk = (kt) * BK + ldc;                                              \
        _Pragma("unroll")                                                      \
        for (int r = 0; r < 8; r++) {                                          \
            int row = ldrow + r * 32;                                          \
            uint32_t sa = (uint32_t)__cvta_generic_to_shared(                  \
                &Asm[(st) * A_STAGE + row * HSTRIDE + ldc]);                   \
            const __half* ga = A + (size_t)(bm + row) * IN_F + gk;             \
            asm volatile("cp.async.cg.shared.global [%0], [%1], 16;\n"         \
                         :: "r"(sa), "l"(ga));                                 \
        }                                                                      \
        _Pragma("unroll")                                                      \
        for (int r = 0; r < 4; r++) {                                          \
            int row = ldrow + r * 32;                                          \
            uint32_t sb = (uint32_t)__cvta_generic_to_shared(                  \
                &Bsm[(st) * B_STAGE + row * HSTRIDE + ldc]);                   \
            const __half* gb = Bw + (size_t)(bn + row) * IN_F + gk;            \
            asm volatile("cp.async.cg.shared.global [%0], [%1], 16;\n"         \
                         :: "r"(sb), "l"(gb));                                 \
        }                                                                      \
    } while (0)

    // prefetch 2 stages
    LOAD_TILE(0, 0);
    asm volatile("cp.async.commit_group;\n");
    LOAD_TILE(1, 1);
    asm volatile("cp.async.commit_group;\n");

    int st = 0;        // stage holding tile kt
    int ld = 2;        // stage to load tile kt+2 into

#pragma unroll 1
    for (int kt = 0; kt < NT; kt++) {
        asm volatile("cp.async.wait_group 1;\n");   // tile kt complete
        __syncthreads();   // all warps done with stage 'ld'

        if (kt + 2 < NT) LOAD_TILE(ld, kt + 2);
        asm volatile("cp.async.commit_group;\n");   // always commit: exact group count

        const __half* as = &Asm[st * A_STAGE];
        const __half* bs = &Bsm[st * B_STAGE];

#pragma unroll
        for (int kk = 0; kk < BK; kk += 16) {
            uint32_t af[4][4], bf[8][2];
#pragma unroll
            for (int mt = 0; mt < 4; mt++) {
                int row = wm + mt * 16 + grp;
                af[mt][0] = *reinterpret_cast<const uint32_t*>(&as[row * HSTRIDE + kk + 2 * tig]);
                af[mt][1] = *reinterpret_cast<const uint32_t*>(&as[(row + 8) * HSTRIDE + kk + 2 * tig]);
                af[mt][2] = *reinterpret_cast<const uint32_t*>(&as[row * HSTRIDE + kk + 2 * tig + 8]);
                af[mt][3] = *reinterpret_cast<const uint32_t*>(&as[(row + 8) * HSTRIDE + kk + 2 * tig + 8]);
            }
#pragma unroll
            for (int nt = 0; nt < 8; nt++) {
                int col = wn + nt * 8 + grp;
                bf[nt][0] = *reinterpret_cast<const uint32_t*>(&bs[col * HSTRIDE + kk + 2 * tig]);
                bf[nt][1] = *reinterpret_cast<const uint32_t*>(&bs[col * HSTRIDE + kk + 2 * tig + 8]);
            }
#pragma unroll
            for (int mt = 0; mt < 4; mt++)
#pragma unroll
                for (int nt = 0; nt < 8; nt++) {
                    asm volatile(
                        "mma.sync.aligned.m16n8k16.row.col.f32.f16.f16.f32 "
                        "{%0,%1,%2,%3}, {%4,%5,%6,%7}, {%8,%9}, {%0,%1,%2,%3};\n"
                        : "+f"(c[mt][nt][0]), "+f"(c[mt][nt][1]),
                          "+f"(c[mt][nt][2]), "+f"(c[mt][nt][3])
                        : "r"(af[mt][0]), "r"(af[mt][1]),
                          "r"(af[mt][2]), "r"(af[mt][3]),
                          "r"(bf[nt][0]), "r"(bf[nt][1]));
                }
        }

        // rotate stages (mod 3)
        st = (st == STAGES - 1) ? 0 : st + 1;
        ld = (ld == STAGES - 1) ? 0 : ld + 1;
    }

    // Epilogue: add bias, float2 stores (cols 2*tig, 2*tig+1 contiguous)
#pragma unroll
    for (int nt = 0; nt < 8; nt++) {
        int col = bn + wn + nt * 8 + tig * 2;
        float b0 = __ldg(bias + col);
        float b1 = __ldg(bias + col + 1);
#pragma unroll
        for (int mt = 0; mt < 4; mt++) {
            int row0 = bm + wm + mt * 16 + grp;
            float2 v0 = make_float2(c[mt][nt][0] + b0, c[mt][nt][1] + b1);
            float2 v1 = make_float2(c[mt][nt][2] + b0, c[mt][nt][3] + b1);
            *reinterpret_cast<float2*>(C + (size_t)row0 * OUT_F + col) = v0;
            *reinterpret_cast<float2*>(C + (size_t)(row0 + 8) * OUT_F + col) = v1;
        }
    }
}

// ---------------------------------------------------------------------------
// Launch
// ---------------------------------------------------------------------------
extern "C" void kernel_launch(void* const* d_in, const int* in_sizes, int n_in,
                              void* d_out, int out_size) {
    const float* x     = (const float*)d_in[0];  // [16384, 4096] fp32
    const int*   Wq    = (const int*)d_in[1];    // [64, 262144] int32 (u8 values)
    const float* scale = (const float*)d_in[2];  // [1, 262144]
    const float* zero  = (const float*)d_in[3];  // [1, 262144]
    const float* bias  = (const float*)d_in[4];  // [4096]
    float*       out   = (float*)d_out;          // [16384, 4096] fp32

    round_a_kernel<<<(int)((size_t)MDIM * IN_F / 4 / 256), 256>>>(x);
    dequant_kernel<<<(OUT_F * IN_F) / 8 / 256, 256>>>(Wq, scale, zero);

    const int smem_bytes = STAGES * (A_STAGE + B_STAGE) * (int)sizeof(__half);  // 165888
    cudaFuncSetAttribute(gemm_f16_kernel,
                         cudaFuncAttributeMaxDynamicSharedMemorySize, smem_bytes);

    dim3 grid(OUT_F / BN, MDIM / BM);   // (32, 64)
    gemm_f16_kernel<<<grid, 256, smem_bytes>>>(bias, out);
}